// round 1
// baseline (speedup 1.0000x reference)
#include <cuda_runtime.h>
#include <cuda_bf16.h>

// Cost volume: out[n,c,d,h,w] = left[n,c,h,w] * right[n,c,h,w-d]  (0 if w<d)
// N=2 C=32 H=136 W=240 D=48, fp32.
// Strategy: 1 CTA per (n*C+c, h) row. Stage left row + zero-prefix-padded right
// row in smem, then stream 48 disparity rows out with float4 stores.
// Write-bound: ~401 MB of output traffic.

#define NW 240
#define NH 136
#define NC 32
#define NN 2
#define ND 48
#define W4 (NW / 4)        // 60 float4 per row
#define THREADS 256

__global__ __launch_bounds__(THREADS, 8)
void cost_volume_kernel(const float* __restrict__ left,
                        const float* __restrict__ right,
                        float* __restrict__ out) {
    __shared__ float sL[NW];
    __shared__ float sRp[ND + NW];   // right row with ND-zero prefix pad

    const int b   = blockIdx.x;      // b = nc * NH + h
    const int h   = b % NH;
    const int nc  = b / NH;
    const int tid = threadIdx.x;

    const float* lrow = left  + (size_t)(nc * NH + h) * NW;
    const float* rrow = right + (size_t)(nc * NH + h) * NW;

    // Stage rows. sRp[0..ND) = 0 implements the left zero-pad exactly.
    for (int i = tid; i < ND + NW; i += THREADS)
        sRp[i] = (i < ND) ? 0.0f : rrow[i - ND];
    if (tid < NW)
        sL[tid] = lrow[tid];
    __syncthreads();

    // Output base for this (nc, h): index = (nc*ND + d)*NH*NW + h*NW + w
    float* obase = out + (size_t)nc * ND * NH * NW + (size_t)h * NW;

    const int TOT = ND * W4;         // 2880 float4 stores per CTA
    #pragma unroll 4
    for (int idx = tid; idx < TOT; idx += THREADS) {
        const int d  = idx / W4;
        const int w4 = idx - d * W4;
        const int w  = w4 * 4;
        const int r  = w - d + ND;   // >= 0 always (w>=0, d<=ND)

        float4 v;
        v.x = sL[w + 0] * sRp[r + 0];
        v.y = sL[w + 1] * sRp[r + 1];
        v.z = sL[w + 2] * sRp[r + 2];
        v.w = sL[w + 3] * sRp[r + 3];

        *reinterpret_cast<float4*>(obase + (size_t)d * NH * NW + w) = v;
    }
}

extern "C" void kernel_launch(void* const* d_in, const int* in_sizes, int n_in,
                              void* d_out, int out_size) {
    const float* left  = (const float*)d_in[0];
    const float* right = (const float*)d_in[1];
    float* out = (float*)d_out;

    const int grid = NN * NC * NH;   // 8704 CTAs
    cost_volume_kernel<<<grid, THREADS>>>(left, right, out);
}

// round 2
// speedup vs baseline: 1.0904x; 1.0904x over previous
#include <cuda_runtime.h>
#include <cuda_bf16.h>

// Cost volume: out[n,c,d,h,w] = left[n,c,h,w] * right[n,c,h,w-d]  (0 if w<d)
// N=2 C=32 H=136 W=240 D=48, fp32.
//
// R1 analysis: previous kernel was l1tex-bound (91%) due to 4-way shared bank
// conflicts (lane stride = 4 floats) and 8B of LDS per 4B stored.
// Fix: thread-per-column mapping (lane stride = 1 float -> conflict-free),
// left value cached in a register (48x reuse), one LDS.32 + FMUL + STG.32
// per output. Write traffic (~401 MB) becomes the roofline.

#define NW 240
#define NH 136
#define NC 32
#define NN 2
#define ND 48
#define THREADS 256          // 240 active (one per w column), one row per CTA

__global__ __launch_bounds__(THREADS, 8)
void cost_volume_kernel(const float* __restrict__ left,
                        const float* __restrict__ right,
                        float* __restrict__ out) {
    // Right row with a 48-zero prefix: Rp[j] = (j < 48) ? 0 : rrow[j-48].
    // Then out(w,d) = L[w] * Rp[w - d + 48], valid (and exact) for all w,d.
    __shared__ float sRp[ND + NW];

    const int row = blockIdx.x;          // row = nc * NH + h
    const int h   = row % NH;
    const int nc  = row / NH;
    const int tid = threadIdx.x;

    const float* rrow = right + (size_t)row * NW;

    // Stage the padded right row (conflict-free, coalesced).
    for (int i = tid; i < ND + NW; i += THREADS)
        sRp[i] = (i < ND) ? 0.0f : rrow[i - ND];
    __syncthreads();

    if (tid >= NW) return;               // after the sync: legal

    const int w = tid;
    const float l = left[(size_t)row * NW + w];      // register, reused 48x

    // out index: ((nc*ND + d)*NH + h)*NW + w
    float* optr = out + ((size_t)nc * ND * NH + h) * NW + w;
    const float* rp = sRp + w + ND;      // rp[-d] = Rp[w - d + 48]

    #pragma unroll
    for (int d = 0; d < ND; d++) {
        // Lane-consecutive smem addresses -> conflict-free LDS.32
        optr[(size_t)d * (NH * NW)] = l * rp[-d];
    }
}

extern "C" void kernel_launch(void* const* d_in, const int* in_sizes, int n_in,
                              void* d_out, int out_size) {
    const float* left  = (const float*)d_in[0];
    const float* right = (const float*)d_in[1];
    float* out = (float*)d_out;

    const int grid = NN * NC * NH;       // 8704 CTAs, one per (n,c,h) row
    cost_volume_kernel<<<grid, THREADS>>>(left, right, out);
}